// round 6
// baseline (speedup 1.0000x reference)
#include <cuda_runtime.h>
#include <cstdint>

#define B_    16
#define T_    2048
#define D_    1024
#define TT_   2046
#define MW_   682
#define M_    (B_ * MW_)          // 10912
#define MPAD  11008               // 86 * 128
#define NMUT  64
#define NBIN  32
#define NHEAD 96                  // 64 class + 32 binary (fused)

// -------- device scratch (no allocations allowed; zero-initialized) --------
__device__ float g_wf[MPAD * D_];        // word features, tf32-rounded
__device__ float g_h [MPAD * D_];        // tanh hidden, tf32-rounded
__device__ float g_wt[D_ * D_];          // dense_w, tf32-rounded
__device__ float g_hw[NHEAD * D_];       // fused head weights, tf32-rounded
__device__ float g_hb[NHEAD];            // fused head bias
__device__ int   g_begin[M_];
__device__ int   g_cnt  [M_];

// ===========================================================================
// helpers
// ===========================================================================
__device__ __forceinline__ uint32_t smem_u32(const void* p) {
    return (uint32_t)__cvta_generic_to_shared(p);
}
__device__ __forceinline__ void cp16(uint32_t dst, const void* src) {
    asm volatile("cp.async.cg.shared.global [%0], [%1], 16;\n" :: "r"(dst), "l"(src));
}
#define CP_COMMIT() asm volatile("cp.async.commit_group;" ::: "memory")

__device__ __forceinline__ float f2tf(float x) {
    uint32_t r;
    asm("cvt.rna.tf32.f32 %0, %1;" : "=r"(r) : "f"(x));
    return __uint_as_float(r);
}
__device__ __forceinline__ void mma8(float* c, const uint32_t* a, const uint32_t* b) {
    asm volatile("mma.sync.aligned.m16n8k8.row.col.f32.tf32.tf32.f32 "
        "{%0,%1,%2,%3}, {%4,%5,%6,%7}, {%8,%9}, {%0,%1,%2,%3};"
        : "+f"(c[0]), "+f"(c[1]), "+f"(c[2]), "+f"(c[3])
        : "r"(a[0]), "r"(a[1]), "r"(a[2]), "r"(a[3]), "r"(b[0]), "r"(b[1]));
}

// ===========================================================================
// 1) per-batch scan of word_starts -> word begin token + token count
// ===========================================================================
__global__ void scan_kernel(const int* __restrict__ ws) {
    int b = blockIdx.x;
    const int* w = ws + b * TT_;
    __shared__ int partial[256];
    __shared__ int scnt[MW_];
    int tid = threadIdx.x;
    for (int i = tid; i < MW_; i += 256) scnt[i] = 0;

    int vals[8];
    int s = 0;
#pragma unroll
    for (int i = 0; i < 8; i++) {
        int t = tid * 8 + i;
        int v = (t < TT_) ? w[t] : 0;
        vals[i] = v; s += v;
    }
    partial[tid] = s;
    __syncthreads();
    for (int off = 1; off < 256; off <<= 1) {
        int v = partial[tid];
        int add = (tid >= off) ? partial[tid - off] : 0;
        __syncthreads();
        partial[tid] = v + add;
        __syncthreads();
    }
    int run = (tid > 0) ? partial[tid - 1] : 0;
#pragma unroll
    for (int i = 0; i < 8; i++) {
        int t = tid * 8 + i;
        if (t < TT_) {
            run += vals[i];
            int seg = run - 1;
            if (seg >= 0 && seg < MW_) {
                if (vals[i]) g_begin[b * MW_ + seg] = t;
                atomicAdd(&scnt[seg], 1);
            }
        }
    }
    __syncthreads();
    for (int i = tid; i < MW_; i += 256) g_cnt[b * MW_ + i] = scnt[i];
}

// ===========================================================================
// 2) word-feature segment sums (one block per word), tf32-rounded output
// ===========================================================================
__global__ void wf_kernel(const float* __restrict__ feat) {
    int m = blockIdx.x;
    int b = m / MW_;
    int tid = threadIdx.x;
    int cnt = g_cnt[m];
    float4* out = (float4*)(g_wf + (size_t)m * D_);
    if (cnt == 0) {
        float one = f2tf(1.f);
        out[tid] = make_float4(one, one, one, one);
        return;
    }
    int t0 = g_begin[m];
    const float4* base = (const float4*)(feat + ((size_t)b * T_ + 1 + t0) * D_);
    float4 acc = base[tid];
    for (int i = 1; i < cnt; i++) {
        float4 v = base[(size_t)i * (D_ / 4) + tid];
        acc.x += v.x; acc.y += v.y; acc.z += v.z; acc.w += v.w;
    }
    acc.x = f2tf(acc.x); acc.y = f2tf(acc.y);
    acc.z = f2tf(acc.z); acc.w = f2tf(acc.w);
    out[tid] = acc;
}

// ===========================================================================
// 2b) tf32 round-copy of dense_w
// ===========================================================================
__global__ void roundw_kernel(const float* __restrict__ src) {
    int i = blockIdx.x * 256 + threadIdx.x;     // float4 index
    float4 v = ((const float4*)src)[i];
    v.x = f2tf(v.x); v.y = f2tf(v.y); v.z = f2tf(v.z); v.w = f2tf(v.w);
    ((float4*)g_wt)[i] = v;
}

// ===========================================================================
// 3) fused head weights (tf32-rounded):
//    rows 0..63  = out_w                              bias = out_b
//    rows 64..95 = bin_w[:,64:] + bin_w[:,:64]@out_w  bias = bin_b + bin_w[:,:64]@out_b
// ===========================================================================
__global__ void headw_kernel(const float* __restrict__ out_w, const float* __restrict__ out_b,
                             const float* __restrict__ bin_w, const float* __restrict__ bin_b) {
    int r = blockIdx.x;        // 0..95
    int tid = threadIdx.x;     // 256
    if (r < NMUT) {
        const float* src = out_w + (size_t)r * D_;
        float* dst = g_hw + (size_t)r * D_;
        for (int i = tid; i < D_; i += 256) dst[i] = f2tf(src[i]);
        if (tid == 0) g_hb[r] = out_b[r];
    } else {
        int c = r - NMUT;
        __shared__ float w1[NMUT];
        if (tid < NMUT) w1[tid] = bin_w[(size_t)c * (D_ + NMUT) + tid];
        __syncthreads();
        for (int i = tid; i < D_; i += 256) {
            float acc = bin_w[(size_t)c * (D_ + NMUT) + NMUT + i];
#pragma unroll 8
            for (int j = 0; j < NMUT; j++) acc += w1[j] * out_w[(size_t)j * D_ + i];
            g_hw[(size_t)r * D_ + i] = f2tf(acc);
        }
        if (tid == 0) {
            float bb = bin_b[c];
            for (int j = 0; j < NMUT; j++) bb += w1[j] * out_b[j];
            g_hb[r] = bb;
        }
    }
}

// ===========================================================================
// 4) tf32 mma.sync GEMM:  D[128 x BN] = A[128 x 1024] @ B[BN x 1024]^T
//    BK=16, 3-stage cp.async pipeline (1 barrier/iter), inputs pre-rounded.
//    8 warps (4m x 2n), warp tile 32 x BN/2.
// ===========================================================================
template<int BN, bool TANH>
__global__ __launch_bounds__(256) void tc_gemm(
    const float* __restrict__ A, const float* __restrict__ Bw,
    const float* __restrict__ bias,
    float* __restrict__ O1, float* __restrict__ O2, int Mlim)
{
    constexpr int NF = BN / 16;                 // n-frags per warp
    constexpr int AST = 128 * 20;               // floats per A stage
    constexpr int BST = BN * 20;                // floats per B stage
    extern __shared__ float smem[];
    float* Asm = smem;                          // [3][128][20]
    float* Bsm = smem + 3 * AST;                // [3][BN][20]

    const int tid = threadIdx.x;
    const int lane = tid & 31, wid = tid >> 5;
    const int g = lane >> 2, tg = lane & 3;
    const int wm = (wid & 3) * 32;
    const int wn = (wid >> 2) * (BN / 2);
    const int row0 = blockIdx.y * 128;
    const int col0 = blockIdx.x * BN;

    float acc[2][NF][4];
#pragma unroll
    for (int i = 0; i < 2; i++)
#pragma unroll
        for (int j = 0; j < NF; j++)
#pragma unroll
            for (int q = 0; q < 4; q++) acc[i][j][q] = 0.f;

    const float* Ab = A + (size_t)row0 * D_;
    const float* Bb = Bw + (size_t)col0 * D_;

    auto loadStage = [&](int st, int k0) {
        float* Ad = Asm + st * AST;
#pragma unroll
        for (int i = tid; i < 512; i += 256) {
            int r = i >> 2, c = i & 3;
            cp16(smem_u32(Ad + r * 20 + c * 4), Ab + (size_t)r * D_ + k0 + c * 4);
        }
        float* Bd = Bsm + st * BST;
        for (int i = tid; i < BN * 4; i += 256) {
            int r = i >> 2, c = i & 3;
            cp16(smem_u32(Bd + r * 20 + c * 4), Bb + (size_t)r * D_ + k0 + c * 4);
        }
        CP_COMMIT();
    };
    auto compute = [&](int st) {
        const float* Ad = Asm + st * AST;
        const float* Bd = Bsm + st * BST;
#pragma unroll
        for (int ks = 0; ks < 2; ks++) {
            const int kk = ks * 8;
            uint32_t a[2][4];
#pragma unroll
            for (int i = 0; i < 2; i++) {
                const float* ap = Ad + (wm + i * 16 + g) * 20 + kk + tg;
                a[i][0] = __float_as_uint(ap[0]);
                a[i][1] = __float_as_uint(ap[8 * 20]);
                a[i][2] = __float_as_uint(ap[4]);
                a[i][3] = __float_as_uint(ap[8 * 20 + 4]);
            }
#pragma unroll
            for (int j = 0; j < NF; j++) {
                const float* bp = Bd + (wn + j * 8 + g) * 20 + kk + tg;
                uint32_t b[2];
                b[0] = __float_as_uint(bp[0]);
                b[1] = __float_as_uint(bp[4]);
                mma8(acc[0][j], a[0], b);
                mma8(acc[1][j], a[1], b);
            }
        }
    };

    // 3-stage pipeline, one barrier per iteration
    loadStage(0, 0);
    loadStage(1, 16);
    int st = 0;
    for (int k0 = 0; k0 < D_; k0 += 16) {
        asm volatile("cp.async.wait_group 1;" ::: "memory");
        __syncthreads();
        if (k0 + 32 < D_) {
            int nst = st + 2; if (nst >= 3) nst -= 3;
            loadStage(nst, k0 + 32);
        }
        compute(st);
        st = (st == 2) ? 0 : st + 1;
    }

    // ---- epilogue ----
#pragma unroll
    for (int i = 0; i < 2; i++) {
#pragma unroll
        for (int j = 0; j < NF; j++) {
            int r = row0 + wm + i * 16 + g;
            int c = col0 + wn + j * 8 + tg * 2;
            if (TANH) {
                float2 v0, v1;
                v0.x = f2tf(tanhf(acc[i][j][0] + bias[c]));
                v0.y = f2tf(tanhf(acc[i][j][1] + bias[c + 1]));
                v1.x = f2tf(tanhf(acc[i][j][2] + bias[c]));
                v1.y = f2tf(tanhf(acc[i][j][3] + bias[c + 1]));
                *(float2*)(O1 + (size_t)r * D_ + c) = v0;
                *(float2*)(O1 + (size_t)(r + 8) * D_ + c) = v1;
            } else {
#pragma unroll
                for (int rr = 0; rr < 2; rr++) {
                    int row = r + rr * 8;
                    if (row < Mlim) {
                        float x0 = acc[i][j][rr * 2 + 0] + bias[c];
                        float x1 = acc[i][j][rr * 2 + 1] + bias[c + 1];
                        if (c < NMUT) {
                            O1[(size_t)row * NMUT + c] = x0;
                            O1[(size_t)row * NMUT + c + 1] = x1;
                        } else {
                            O2[(size_t)row * NBIN + (c - NMUT)] = x0;
                            O2[(size_t)row * NBIN + (c - NMUT) + 1] = x1;
                        }
                    }
                }
            }
        }
    }
}

// ===========================================================================
extern "C" void kernel_launch(void* const* d_in, const int* in_sizes, int n_in,
                              void* d_out, int out_size)
{
    const float* features = (const float*)d_in[0];
    const int*   wstarts  = (const int*)d_in[1];
    const float* dense_w  = (const float*)d_in[2];
    const float* dense_b  = (const float*)d_in[3];
    const float* out_w    = (const float*)d_in[4];
    const float* out_b    = (const float*)d_in[5];
    const float* bin_w    = (const float*)d_in[6];
    const float* bin_b    = (const float*)d_in[7];
    (void)in_sizes; (void)n_in; (void)out_size;

    float *wf, *h, *wt, *hw, *hb;
    cudaGetSymbolAddress((void**)&wf, g_wf);
    cudaGetSymbolAddress((void**)&h,  g_h);
    cudaGetSymbolAddress((void**)&wt, g_wt);
    cudaGetSymbolAddress((void**)&hw, g_hw);
    cudaGetSymbolAddress((void**)&hb, g_hb);

    float* wcl = (float*)d_out;                        // [M, 64]
    float* bin = (float*)d_out + (size_t)M_ * NMUT;    // [M, 32]

    const int SMEM_MAIN = 3 * (128 * 20 + 128 * 20) * 4;   // 61440
    const int SMEM_HEAD = 3 * (128 * 20 + 96 * 20) * 4;    // 53760
    cudaFuncSetAttribute(tc_gemm<128, true>,
                         cudaFuncAttributeMaxDynamicSharedMemorySize, SMEM_MAIN);
    cudaFuncSetAttribute(tc_gemm<96, false>,
                         cudaFuncAttributeMaxDynamicSharedMemorySize, SMEM_HEAD);

    scan_kernel<<<B_, 256>>>(wstarts);
    wf_kernel<<<M_, 256>>>(features);
    roundw_kernel<<<D_ * D_ / 4 / 256, 256>>>(dense_w);
    headw_kernel<<<NHEAD, 256>>>(out_w, out_b, bin_w, bin_b);

    // h = tanh(wf @ dense_w^T + dense_b)
    tc_gemm<128, true><<<dim3(8, MPAD / 128), 256, SMEM_MAIN>>>(
        wf, wt, dense_b, h, nullptr, MPAD);
    // [wcl | bin] = h @ g_hw^T + g_hb
    tc_gemm<96, false><<<dim3(1, MPAD / 128), 256, SMEM_HEAD>>>(
        h, hw, hb, wcl, bin, M_);
}

// round 7
// speedup vs baseline: 1.0657x; 1.0657x over previous
#include <cuda_runtime.h>
#include <cstdint>

#define B_    16
#define T_    2048
#define D_    1024
#define TT_   2046
#define MW_   682
#define M_    (B_ * MW_)          // 10912
#define MPAD  11008               // 86 * 128
#define NMUT  64
#define NBIN  32
#define NHEAD 96                  // 64 class + 32 binary (fused)

// -------- device scratch (no allocations allowed; zero-initialized) --------
__device__ float g_wf[MPAD * D_];        // word features, tf32-rounded
__device__ float g_h [MPAD * D_];        // tanh hidden, tf32-rounded
__device__ float g_wt[D_ * D_];          // dense_w, tf32-rounded
__device__ float g_hw[NHEAD * D_];       // fused head weights, tf32-rounded
__device__ float g_hb[NHEAD];            // fused head bias
__device__ int   g_begin[M_];
__device__ int   g_cnt  [M_];

// ===========================================================================
// helpers
// ===========================================================================
__device__ __forceinline__ uint32_t smem_u32(const void* p) {
    return (uint32_t)__cvta_generic_to_shared(p);
}
__device__ __forceinline__ void cp16(uint32_t dst, const void* src) {
    asm volatile("cp.async.cg.shared.global [%0], [%1], 16;\n" :: "r"(dst), "l"(src));
}
#define CP_COMMIT() asm volatile("cp.async.commit_group;" ::: "memory")

__device__ __forceinline__ float f2tf(float x) {
    uint32_t r;
    asm("cvt.rna.tf32.f32 %0, %1;" : "=r"(r) : "f"(x));
    return __uint_as_float(r);
}
__device__ __forceinline__ void mma8(float* c, const uint32_t* a, const uint32_t* b) {
    asm volatile("mma.sync.aligned.m16n8k8.row.col.f32.tf32.tf32.f32 "
        "{%0,%1,%2,%3}, {%4,%5,%6,%7}, {%8,%9}, {%0,%1,%2,%3};"
        : "+f"(c[0]), "+f"(c[1]), "+f"(c[2]), "+f"(c[3])
        : "r"(a[0]), "r"(a[1]), "r"(a[2]), "r"(a[3]), "r"(b[0]), "r"(b[1]));
}

// ===========================================================================
// 1) per-batch scan of word_starts -> word begin token + token count
// ===========================================================================
__global__ void scan_kernel(const int* __restrict__ ws) {
    int b = blockIdx.x;
    const int* w = ws + b * TT_;
    __shared__ int partial[256];
    __shared__ int scnt[MW_];
    int tid = threadIdx.x;
    for (int i = tid; i < MW_; i += 256) scnt[i] = 0;

    int vals[8];
    int s = 0;
#pragma unroll
    for (int i = 0; i < 8; i++) {
        int t = tid * 8 + i;
        int v = (t < TT_) ? w[t] : 0;
        vals[i] = v; s += v;
    }
    partial[tid] = s;
    __syncthreads();
    for (int off = 1; off < 256; off <<= 1) {
        int v = partial[tid];
        int add = (tid >= off) ? partial[tid - off] : 0;
        __syncthreads();
        partial[tid] = v + add;
        __syncthreads();
    }
    int run = (tid > 0) ? partial[tid - 1] : 0;
#pragma unroll
    for (int i = 0; i < 8; i++) {
        int t = tid * 8 + i;
        if (t < TT_) {
            run += vals[i];
            int seg = run - 1;
            if (seg >= 0 && seg < MW_) {
                if (vals[i]) g_begin[b * MW_ + seg] = t;
                atomicAdd(&scnt[seg], 1);
            }
        }
    }
    __syncthreads();
    for (int i = tid; i < MW_; i += 256) g_cnt[b * MW_ + i] = scnt[i];
}

// ===========================================================================
// 2) word-feature segment sums (one block per word), tf32-rounded output
// ===========================================================================
__global__ void wf_kernel(const float* __restrict__ feat) {
    int m = blockIdx.x;
    int b = m / MW_;
    int tid = threadIdx.x;
    int cnt = g_cnt[m];
    float4* out = (float4*)(g_wf + (size_t)m * D_);
    if (cnt == 0) {
        float one = f2tf(1.f);
        out[tid] = make_float4(one, one, one, one);
        return;
    }
    int t0 = g_begin[m];
    const float4* base = (const float4*)(feat + ((size_t)b * T_ + 1 + t0) * D_);
    float4 acc = base[tid];
    for (int i = 1; i < cnt; i++) {
        float4 v = base[(size_t)i * (D_ / 4) + tid];
        acc.x += v.x; acc.y += v.y; acc.z += v.z; acc.w += v.w;
    }
    acc.x = f2tf(acc.x); acc.y = f2tf(acc.y);
    acc.z = f2tf(acc.z); acc.w = f2tf(acc.w);
    out[tid] = acc;
}

// ===========================================================================
// 2b) tf32 round-copy of dense_w
// ===========================================================================
__global__ void roundw_kernel(const float* __restrict__ src) {
    int i = blockIdx.x * 256 + threadIdx.x;     // float4 index
    float4 v = ((const float4*)src)[i];
    v.x = f2tf(v.x); v.y = f2tf(v.y); v.z = f2tf(v.z); v.w = f2tf(v.w);
    ((float4*)g_wt)[i] = v;
}

// ===========================================================================
// 3a) g_hw rows 0..63 = round(out_w); g_hb[0..63] = out_b
// ===========================================================================
__global__ void headw_copy(const float* __restrict__ out_w, const float* __restrict__ out_b) {
    int i = blockIdx.x * 256 + threadIdx.x;     // float4 index over 64*1024
    float4 v = ((const float4*)out_w)[i];
    v.x = f2tf(v.x); v.y = f2tf(v.y); v.z = f2tf(v.z); v.w = f2tf(v.w);
    ((float4*)g_hw)[i] = v;
    if (blockIdx.x == 0 && threadIdx.x < NMUT) g_hb[threadIdx.x] = out_b[threadIdx.x];
}

// ===========================================================================
// 3b) g_hw rows 64..95 = round(bin_w[:,64:] + bin_w[:,:64] @ out_w)
//     g_hb[64..95]     = bin_b + bin_w[:,:64] @ out_b
//     8 blocks, each owns a 128-column slice; out_w read exactly once.
// ===========================================================================
__global__ void headw_bin(const float* __restrict__ out_w, const float* __restrict__ out_b,
                          const float* __restrict__ bin_w, const float* __restrict__ bin_b) {
    __shared__ float w1[NBIN][NMUT];
    int tid = threadIdx.x;
    int col0 = blockIdx.x * 128;
    for (int i = tid; i < NBIN * NMUT; i += 256) {
        int r = i >> 6, j = i & 63;
        w1[r][j] = bin_w[(size_t)r * (D_ + NMUT) + j];
    }
    __syncthreads();

    int col = col0 + (tid & 127);
    int rh  = (tid >> 7) * 16;                 // rows rh..rh+15
    float acc[16];
#pragma unroll
    for (int r = 0; r < 16; r++)
        acc[r] = bin_w[(size_t)(rh + r) * (D_ + NMUT) + NMUT + col];
    for (int j = 0; j < NMUT; j++) {
        float v = out_w[(size_t)j * D_ + col];
#pragma unroll
        for (int r = 0; r < 16; r++) acc[r] += w1[rh + r][j] * v;
    }
#pragma unroll
    for (int r = 0; r < 16; r++)
        g_hw[(size_t)(NMUT + rh + r) * D_ + col] = f2tf(acc[r]);

    if (blockIdx.x == 0 && tid < NBIN) {
        float bb = bin_b[tid];
        for (int j = 0; j < NMUT; j++) bb += w1[tid][j] * out_b[j];
        g_hb[NMUT + tid] = bb;
    }
}

// ===========================================================================
// 4) tf32 mma.sync GEMM:  D[128 x BN] = A[128 x 1024] @ B[BN x 1024]^T
//    BK=32, 2-stage cp.async double buffer, 1 barrier per 32-k chunk.
//    8 warps (4m x 2n), warp tile 32 x BN/2. Row stride 36 => conflict-free.
// ===========================================================================
template<int BN, bool TANH>
__global__ __launch_bounds__(256) void tc_gemm(
    const float* __restrict__ A, const float* __restrict__ Bw,
    const float* __restrict__ bias,
    float* __restrict__ O1, float* __restrict__ O2, int Mlim)
{
    constexpr int NF = BN / 16;                 // n-frags per warp
    constexpr int AST = 128 * 36;               // floats per A stage
    constexpr int BST = BN * 36;                // floats per B stage
    extern __shared__ float smem[];
    float* Asm = smem;                          // [2][128][36]
    float* Bsm = smem + 2 * AST;                // [2][BN][36]

    const int tid = threadIdx.x;
    const int lane = tid & 31, wid = tid >> 5;
    const int g = lane >> 2, tg = lane & 3;
    const int wm = (wid & 3) * 32;
    const int wn = (wid >> 2) * (BN / 2);
    const int row0 = blockIdx.y * 128;
    const int col0 = blockIdx.x * BN;

    float acc[2][NF][4];
#pragma unroll
    for (int i = 0; i < 2; i++)
#pragma unroll
        for (int j = 0; j < NF; j++)
#pragma unroll
            for (int q = 0; q < 4; q++) acc[i][j][q] = 0.f;

    const float* Ab = A + (size_t)row0 * D_;
    const float* Bb = Bw + (size_t)col0 * D_;

    auto loadStage = [&](int st, int k0) {
        float* Ad = Asm + st * AST;
#pragma unroll
        for (int i = tid; i < 1024; i += 256) {
            int r = i >> 3, c = i & 7;
            cp16(smem_u32(Ad + r * 36 + c * 4), Ab + (size_t)r * D_ + k0 + c * 4);
        }
        float* Bd = Bsm + st * BST;
        for (int i = tid; i < BN * 8; i += 256) {
            int r = i >> 3, c = i & 7;
            cp16(smem_u32(Bd + r * 36 + c * 4), Bb + (size_t)r * D_ + k0 + c * 4);
        }
        CP_COMMIT();
    };
    auto compute = [&](int st) {
        const float* Ad = Asm + st * AST;
        const float* Bd = Bsm + st * BST;
#pragma unroll
        for (int ks = 0; ks < 4; ks++) {
            const int kk = ks * 8;
            uint32_t a[2][4];
#pragma unroll
            for (int i = 0; i < 2; i++) {
                const float* ap = Ad + (wm + i * 16 + g) * 36 + kk + tg;
                a[i][0] = __float_as_uint(ap[0]);
                a[i][1] = __float_as_uint(ap[8 * 36]);
                a[i][2] = __float_as_uint(ap[4]);
                a[i][3] = __float_as_uint(ap[8 * 36 + 4]);
            }
#pragma unroll
            for (int j = 0; j < NF; j++) {
                const float* bp = Bd + (wn + j * 8 + g) * 36 + kk + tg;
                uint32_t b[2];
                b[0] = __float_as_uint(bp[0]);
                b[1] = __float_as_uint(bp[4]);
                mma8(acc[0][j], a[0], b);
                mma8(acc[1][j], a[1], b);
            }
        }
    };

    // 2-stage double buffer: prefetch next chunk, one barrier per chunk
    loadStage(0, 0);
    int st = 0;
    for (int k0 = 0; k0 < D_; k0 += 32) {
        asm volatile("cp.async.wait_group 0;" ::: "memory");
        __syncthreads();
        if (k0 + 32 < D_) loadStage(st ^ 1, k0 + 32);
        compute(st);
        st ^= 1;
    }

    // ---- epilogue ----
#pragma unroll
    for (int i = 0; i < 2; i++) {
#pragma unroll
        for (int j = 0; j < NF; j++) {
            int r = row0 + wm + i * 16 + g;
            int c = col0 + wn + j * 8 + tg * 2;
            if (TANH) {
                float2 v0, v1;
                v0.x = f2tf(tanhf(acc[i][j][0] + bias[c]));
                v0.y = f2tf(tanhf(acc[i][j][1] + bias[c + 1]));
                v1.x = f2tf(tanhf(acc[i][j][2] + bias[c]));
                v1.y = f2tf(tanhf(acc[i][j][3] + bias[c + 1]));
                *(float2*)(O1 + (size_t)r * D_ + c) = v0;
                *(float2*)(O1 + (size_t)(r + 8) * D_ + c) = v1;
            } else {
#pragma unroll
                for (int rr = 0; rr < 2; rr++) {
                    int row = r + rr * 8;
                    if (row < Mlim) {
                        float x0 = acc[i][j][rr * 2 + 0] + bias[c];
                        float x1 = acc[i][j][rr * 2 + 1] + bias[c + 1];
                        if (c < NMUT) {
                            O1[(size_t)row * NMUT + c] = x0;
                            O1[(size_t)row * NMUT + c + 1] = x1;
                        } else {
                            O2[(size_t)row * NBIN + (c - NMUT)] = x0;
                            O2[(size_t)row * NBIN + (c - NMUT) + 1] = x1;
                        }
                    }
                }
            }
        }
    }
}

// ===========================================================================
extern "C" void kernel_launch(void* const* d_in, const int* in_sizes, int n_in,
                              void* d_out, int out_size)
{
    const float* features = (const float*)d_in[0];
    const int*   wstarts  = (const int*)d_in[1];
    const float* dense_w  = (const float*)d_in[2];
    const float* dense_b  = (const float*)d_in[3];
    const float* out_w    = (const float*)d_in[4];
    const float* out_b    = (const float*)d_in[5];
    const float* bin_w    = (const float*)d_in[6];
    const float* bin_b    = (const float*)d_in[7];
    (void)in_sizes; (void)n_in; (void)out_size;

    float *wf, *h, *wt, *hw, *hb;
    cudaGetSymbolAddress((void**)&wf, g_wf);
    cudaGetSymbolAddress((void**)&h,  g_h);
    cudaGetSymbolAddress((void**)&wt, g_wt);
    cudaGetSymbolAddress((void**)&hw, g_hw);
    cudaGetSymbolAddress((void**)&hb, g_hb);

    float* wcl = (float*)d_out;                        // [M, 64]
    float* bin = (float*)d_out + (size_t)M_ * NMUT;    // [M, 32]

    const int SMEM_MAIN = 2 * (128 * 36 + 128 * 36) * 4;   // 73728
    const int SMEM_HEAD = 2 * (128 * 36 + 96 * 36) * 4;    // 64512
    cudaFuncSetAttribute(tc_gemm<128, true>,
                         cudaFuncAttributeMaxDynamicSharedMemorySize, SMEM_MAIN);
    cudaFuncSetAttribute(tc_gemm<96, false>,
                         cudaFuncAttributeMaxDynamicSharedMemorySize, SMEM_HEAD);

    scan_kernel<<<B_, 256>>>(wstarts);
    wf_kernel<<<M_, 256>>>(features);
    roundw_kernel<<<D_ * D_ / 4 / 256, 256>>>(dense_w);
    headw_copy<<<NMUT * D_ / 4 / 256, 256>>>(out_w, out_b);
    headw_bin<<<8, 256>>>(out_w, out_b, bin_w, bin_b);

    // h = tanh(wf @ dense_w^T + dense_b)
    tc_gemm<128, true><<<dim3(8, MPAD / 128), 256, SMEM_MAIN>>>(
        wf, wt, dense_b, h, nullptr, MPAD);
    // [wcl | bin] = h @ g_hw^T + g_hb
    tc_gemm<96, false><<<dim3(1, MPAD / 128), 256, SMEM_HEAD>>>(
        h, hw, hb, wcl, bin, M_);
}

// round 8
// speedup vs baseline: 1.0741x; 1.0079x over previous
#include <cuda_runtime.h>
#include <cstdint>

#define B_    16
#define T_    2048
#define D_    1024
#define TT_   2046
#define MW_   682
#define M_    (B_ * MW_)          // 10912
#define MPAD  11008               // 86 * 128 = 172 * 64
#define NMUT  64
#define NBIN  32
#define NHEAD 96                  // 64 class + 32 binary (fused)

// NOTE: all GEMM operand tensors below are stored with each 8-wide k-group
// permuted: logical k -> storage position p(k) = 2*(k&3) | (k>>2).
// This makes mma fragment k-pairs (tg, tg+4) adjacent -> LDS.64 loads.
__device__ float g_wf[MPAD * D_];        // word features, tf32, k-permuted
__device__ float g_h [MPAD * D_];        // tanh hidden, tf32, k-permuted
__device__ float g_wt[D_ * D_];          // dense_w, tf32, k-permuted
__device__ float g_hw[NHEAD * D_];       // fused head weights, tf32, k-permuted
__device__ float g_hb[NHEAD];            // fused head bias
__device__ int   g_begin[M_];
__device__ int   g_cnt  [M_];

// ===========================================================================
// helpers
// ===========================================================================
__device__ __forceinline__ uint32_t smem_u32(const void* p) {
    return (uint32_t)__cvta_generic_to_shared(p);
}
__device__ __forceinline__ void cp16(uint32_t dst, const void* src) {
    asm volatile("cp.async.cg.shared.global [%0], [%1], 16;\n" :: "r"(dst), "l"(src));
}
#define CP_COMMIT() asm volatile("cp.async.commit_group;" ::: "memory")

__device__ __forceinline__ float f2tf(float x) {
    uint32_t r;
    asm("cvt.rna.tf32.f32 %0, %1;" : "=r"(r) : "f"(x));
    return __uint_as_float(r);
}
__device__ __forceinline__ int kperm8(int l) {       // l in 0..7
    return ((l & 3) << 1) | (l >> 2);
}
__device__ __forceinline__ void mma8(float* c, const uint32_t* a, const uint32_t* b) {
    asm volatile("mma.sync.aligned.m16n8k8.row.col.f32.tf32.tf32.f32 "
        "{%0,%1,%2,%3}, {%4,%5,%6,%7}, {%8,%9}, {%0,%1,%2,%3};"
        : "+f"(c[0]), "+f"(c[1]), "+f"(c[2]), "+f"(c[3])
        : "r"(a[0]), "r"(a[1]), "r"(a[2]), "r"(a[3]), "r"(b[0]), "r"(b[1]));
}

// ===========================================================================
// 1) per-batch scan of word_starts -> word begin token + token count
// ===========================================================================
__global__ void scan_kernel(const int* __restrict__ ws) {
    int b = blockIdx.x;
    const int* w = ws + b * TT_;
    __shared__ int partial[256];
    __shared__ int scnt[MW_];
    int tid = threadIdx.x;
    for (int i = tid; i < MW_; i += 256) scnt[i] = 0;

    int vals[8];
    int s = 0;
#pragma unroll
    for (int i = 0; i < 8; i++) {
        int t = tid * 8 + i;
        int v = (t < TT_) ? w[t] : 0;
        vals[i] = v; s += v;
    }
    partial[tid] = s;
    __syncthreads();
    for (int off = 1; off < 256; off <<= 1) {
        int v = partial[tid];
        int add = (tid >= off) ? partial[tid - off] : 0;
        __syncthreads();
        partial[tid] = v + add;
        __syncthreads();
    }
    int run = (tid > 0) ? partial[tid - 1] : 0;
#pragma unroll
    for (int i = 0; i < 8; i++) {
        int t = tid * 8 + i;
        if (t < TT_) {
            run += vals[i];
            int seg = run - 1;
            if (seg >= 0 && seg < MW_) {
                if (vals[i]) g_begin[b * MW_ + seg] = t;
                atomicAdd(&scnt[seg], 1);
            }
        }
    }
    __syncthreads();
    for (int i = tid; i < MW_; i += 256) g_cnt[b * MW_ + i] = scnt[i];
}

// ===========================================================================
// 2) word-feature segment sums, tf32-rounded, k-permuted store
// ===========================================================================
__global__ void wf_kernel(const float* __restrict__ feat) {
    int m = blockIdx.x;
    int b = m / MW_;
    int tid = threadIdx.x;                       // float4 index 0..255
    int cnt = g_cnt[m];
    float* orow = g_wf + (size_t)m * D_;
    int base8 = (4 * tid) & ~7;
    int o = tid & 1;
    float* dst = orow + base8 + o;
    if (cnt == 0) {
        float one = f2tf(1.f);
        dst[0] = one; dst[2] = one; dst[4] = one; dst[6] = one;
        return;
    }
    int t0 = g_begin[m];
    const float4* base = (const float4*)(feat + ((size_t)b * T_ + 1 + t0) * D_);
    float4 acc = base[tid];
    for (int i = 1; i < cnt; i++) {
        float4 v = base[(size_t)i * (D_ / 4) + tid];
        acc.x += v.x; acc.y += v.y; acc.z += v.z; acc.w += v.w;
    }
    dst[0] = f2tf(acc.x); dst[2] = f2tf(acc.y);
    dst[4] = f2tf(acc.z); dst[6] = f2tf(acc.w);
}

// ===========================================================================
// 2b) tf32 round-copy of dense_w, k-permuted
// ===========================================================================
__global__ void roundw_kernel(const float* __restrict__ src) {
    int i = blockIdx.x * 256 + threadIdx.x;      // float4 index
    float4 v = ((const float4*)src)[i];
    int base8 = (4 * i) & ~7;
    int o = i & 1;
    float* dst = g_wt + base8 + o;
    dst[0] = f2tf(v.x); dst[2] = f2tf(v.y); dst[4] = f2tf(v.z); dst[6] = f2tf(v.w);
}

// ===========================================================================
// 3a) g_hw rows 0..63 = round(out_w) k-permuted; g_hb[0..63] = out_b
// ===========================================================================
__global__ void headw_copy(const float* __restrict__ out_w, const float* __restrict__ out_b) {
    int i = blockIdx.x * 256 + threadIdx.x;      // float4 index over 64*1024
    float4 v = ((const float4*)out_w)[i];
    int base8 = (4 * i) & ~7;
    int o = i & 1;
    float* dst = g_hw + base8 + o;
    dst[0] = f2tf(v.x); dst[2] = f2tf(v.y); dst[4] = f2tf(v.z); dst[6] = f2tf(v.w);
    if (blockIdx.x == 0 && threadIdx.x < NMUT) g_hb[threadIdx.x] = out_b[threadIdx.x];
}

// ===========================================================================
// 3b) g_hw rows 64..95 = round(bin_w[:,64:] + bin_w[:,:64] @ out_w), k-permuted
//     g_hb[64..95]     = bin_b + bin_w[:,:64] @ out_b
// ===========================================================================
__global__ void headw_bin(const float* __restrict__ out_w, const float* __restrict__ out_b,
                          const float* __restrict__ bin_w, const float* __restrict__ bin_b) {
    __shared__ float w1[NBIN][NMUT];
    int tid = threadIdx.x;
    int col0 = blockIdx.x * 128;
    for (int i = tid; i < NBIN * NMUT; i += 256) {
        int r = i >> 6, j = i & 63;
        w1[r][j] = bin_w[(size_t)r * (D_ + NMUT) + j];
    }
    __syncthreads();

    int col = col0 + (tid & 127);
    int rh  = (tid >> 7) * 16;
    float acc[16];
#pragma unroll
    for (int r = 0; r < 16; r++)
        acc[r] = bin_w[(size_t)(rh + r) * (D_ + NMUT) + NMUT + col];
    for (int j = 0; j < NMUT; j++) {
        float v = out_w[(size_t)j * D_ + col];
#pragma unroll
        for (int r = 0; r < 16; r++) acc[r] += w1[rh + r][j] * v;
    }
    int pc = (col & ~7) | kperm8(col & 7);
#pragma unroll
    for (int r = 0; r < 16; r++)
        g_hw[(size_t)(NMUT + rh + r) * D_ + pc] = f2tf(acc[r]);

    if (blockIdx.x == 0 && tid < NBIN) {
        float bb = bin_b[tid];
        for (int j = 0; j < NMUT; j++) bb += w1[tid][j] * out_b[j];
        g_hb[NMUT + tid] = bb;
    }
}

// ===========================================================================
// 4) main tf32 GEMM: h = tanh(wf @ wt^T + b), 128x128 tile, BK=32, 2-stage.
//    Operands k-permuted => LDS.64 fragment loads. Row stride 40.
// ===========================================================================
__global__ __launch_bounds__(256) void tc_main(
    const float* __restrict__ A, const float* __restrict__ Bw,
    const float* __restrict__ bias, float* __restrict__ O1)
{
    constexpr int AST = 128 * 40;
    constexpr int BST = 128 * 40;
    extern __shared__ float smem[];
    float* Asm = smem;                           // [2][128][40]
    float* Bsm = smem + 2 * AST;                 // [2][128][40]

    const int tid = threadIdx.x;
    const int lane = tid & 31, wid = tid >> 5;
    const int g = lane >> 2, tg = lane & 3;
    const int wm = (wid & 3) * 32;
    const int wn = (wid >> 2) * 64;
    const int row0 = blockIdx.y * 128;
    const int col0 = blockIdx.x * 128;

    float acc[2][8][4];
#pragma unroll
    for (int i = 0; i < 2; i++)
#pragma unroll
        for (int j = 0; j < 8; j++)
#pragma unroll
            for (int q = 0; q < 4; q++) acc[i][j][q] = 0.f;

    const float* Ab = A + (size_t)row0 * D_;
    const float* Bb = Bw + (size_t)col0 * D_;

    auto loadStage = [&](int st, int k0) {
        float* Ad = Asm + st * AST;
#pragma unroll
        for (int i = tid; i < 1024; i += 256) {
            int r = i >> 3, c = i & 7;
            cp16(smem_u32(Ad + r * 40 + c * 4), Ab + (size_t)r * D_ + k0 + c * 4);
        }
        float* Bd = Bsm + st * BST;
#pragma unroll
        for (int i = tid; i < 1024; i += 256) {
            int r = i >> 3, c = i & 7;
            cp16(smem_u32(Bd + r * 40 + c * 4), Bb + (size_t)r * D_ + k0 + c * 4);
        }
        CP_COMMIT();
    };
    auto compute = [&](int st) {
        const float* Ad = Asm + st * AST;
        const float* Bd = Bsm + st * BST;
#pragma unroll
        for (int ks = 0; ks < 4; ks++) {
            const int kk = ks * 8 + 2 * tg;
            uint32_t a[2][4];
#pragma unroll
            for (int i = 0; i < 2; i++) {
                const float* ap = Ad + (wm + i * 16 + g) * 40 + kk;
                uint2 v0 = *(const uint2*)ap;            // k=tg, k=tg+4
                uint2 v1 = *(const uint2*)(ap + 8 * 40);
                a[i][0] = v0.x; a[i][2] = v0.y;
                a[i][1] = v1.x; a[i][3] = v1.y;
            }
#pragma unroll
            for (int j = 0; j < 8; j++) {
                const float* bp = Bd + (wn + j * 8 + g) * 40 + kk;
                uint2 vb = *(const uint2*)bp;
                uint32_t b[2] = { vb.x, vb.y };
                mma8(acc[0][j], a[0], b);
                mma8(acc[1][j], a[1], b);
            }
        }
    };

    loadStage(0, 0);
    int st = 0;
    for (int k0 = 0; k0 < D_; k0 += 32) {
        asm volatile("cp.async.wait_group 0;" ::: "memory");
        __syncthreads();
        if (k0 + 32 < D_) loadStage(st ^ 1, k0 + 32);
        compute(st);
        st ^= 1;
    }

    // epilogue: bias + tanh, tf32-round, k-permuted scalar stores
#pragma unroll
    for (int i = 0; i < 2; i++) {
#pragma unroll
        for (int j = 0; j < 8; j++) {
            int r = row0 + wm + i * 16 + g;
            int c = col0 + wn + j * 8 + tg * 2;
            int cb = c & ~7;
            int p0 = cb + kperm8(c & 7);
            int p1 = cb + kperm8((c + 1) & 7);
            float x0 = f2tf(tanhf(acc[i][j][0] + bias[c]));
            float x1 = f2tf(tanhf(acc[i][j][1] + bias[c + 1]));
            float x2 = f2tf(tanhf(acc[i][j][2] + bias[c]));
            float x3 = f2tf(tanhf(acc[i][j][3] + bias[c + 1]));
            O1[(size_t)r * D_ + p0] = x0;
            O1[(size_t)r * D_ + p1] = x1;
            O1[(size_t)(r + 8) * D_ + p0] = x2;
            O1[(size_t)(r + 8) * D_ + p1] = x3;
        }
    }
}

// ===========================================================================
// 5) head GEMM: [wcl|bin] = h @ g_hw^T + g_hb.  BM=64, BN=96, BK=32,
//    grid 172 blocks, 8 warps (2m x 4n), warp tile 32x24 (NF=3).
// ===========================================================================
__global__ __launch_bounds__(256) void tc_head(
    const float* __restrict__ A, const float* __restrict__ Bw,
    const float* __restrict__ bias,
    float* __restrict__ O1, float* __restrict__ O2)
{
    constexpr int AST = 64 * 40;
    constexpr int BST = 96 * 40;
    extern __shared__ float smem[];
    float* Asm = smem;                           // [2][64][40]
    float* Bsm = smem + 2 * AST;                 // [2][96][40]

    const int tid = threadIdx.x;
    const int lane = tid & 31, wid = tid >> 5;
    const int g = lane >> 2, tg = lane & 3;
    const int wm = (wid & 1) * 32;
    const int wn = (wid >> 1) * 24;
    const int row0 = blockIdx.x * 64;

    float acc[2][3][4];
#pragma unroll
    for (int i = 0; i < 2; i++)
#pragma unroll
        for (int j = 0; j < 3; j++)
#pragma unroll
            for (int q = 0; q < 4; q++) acc[i][j][q] = 0.f;

    const float* Ab = A + (size_t)row0 * D_;

    auto loadStage = [&](int st, int k0) {
        float* Ad = Asm + st * AST;
#pragma unroll
        for (int i = tid; i < 512; i += 256) {
            int r = i >> 3, c = i & 7;
            cp16(smem_u32(Ad + r * 40 + c * 4), Ab + (size_t)r * D_ + k0 + c * 4);
        }
        float* Bd = Bsm + st * BST;
#pragma unroll
        for (int i = tid; i < 768; i += 256) {
            int r = i >> 3, c = i & 7;
            cp16(smem_u32(Bd + r * 40 + c * 4), Bw + (size_t)r * D_ + k0 + c * 4);
        }
        CP_COMMIT();
    };
    auto compute = [&](int st) {
        const float* Ad = Asm + st * AST;
        const float* Bd = Bsm + st * BST;
#pragma unroll
        for (int ks = 0; ks < 4; ks++) {
            const int kk = ks * 8 + 2 * tg;
            uint32_t a[2][4];
#pragma unroll
            for (int i = 0; i < 2; i++) {
                const float* ap = Ad + (wm + i * 16 + g) * 40 + kk;
                uint2 v0 = *(const uint2*)ap;
                uint2 v1 = *(const uint2*)(ap + 8 * 40);
                a[i][0] = v0.x; a[i][2] = v0.y;
                a[i][1] = v1.x; a[i][3] = v1.y;
            }
#pragma unroll
            for (int j = 0; j < 3; j++) {
                const float* bp = Bd + (wn + j * 8 + g) * 40 + kk;
                uint2 vb = *(const uint2*)bp;
                uint32_t b[2] = { vb.x, vb.y };
                mma8(acc[0][j], a[0], b);
                mma8(acc[1][j], a[1], b);
            }
        }
    };

    loadStage(0, 0);
    int st = 0;
    for (int k0 = 0; k0 < D_; k0 += 32) {
        asm volatile("cp.async.wait_group 0;" ::: "memory");
        __syncthreads();
        if (k0 + 32 < D_) loadStage(st ^ 1, k0 + 32);
        compute(st);
        st ^= 1;
    }

#pragma unroll
    for (int i = 0; i < 2; i++) {
#pragma unroll
        for (int j = 0; j < 3; j++) {
            int c = wn + j * 8 + tg * 2;
#pragma unroll
            for (int rr = 0; rr < 2; rr++) {
                int row = row0 + wm + i * 16 + g + rr * 8;
                if (row < M_) {
                    float x0 = acc[i][j][rr * 2 + 0] + bias[c];
                    float x1 = acc[i][j][rr * 2 + 1] + bias[c + 1];
                    if (c < NMUT) {
                        O1[(size_t)row * NMUT + c] = x0;
                        O1[(size_t)row * NMUT + c + 1] = x1;
                    } else {
                        O2[(size_t)row * NBIN + (c - NMUT)] = x0;
                        O2[(size_t)row * NBIN + (c - NMUT) + 1] = x1;
                    }
                }
            }
        }
    }
}

// ===========================================================================
extern "C" void kernel_launch(void* const* d_in, const int* in_sizes, int n_in,
                              void* d_out, int out_size)
{
    const float* features = (const float*)d_in[0];
    const int*   wstarts  = (const int*)d_in[1];
    const float* dense_w  = (const float*)d_in[2];
    const float* dense_b  = (const float*)d_in[3];
    const float* out_w    = (const float*)d_in[4];
    const float* out_b    = (const float*)d_in[5];
    const float* bin_w    = (const float*)d_in[6];
    const float* bin_b    = (const float*)d_in[7];
    (void)in_sizes; (void)n_in; (void)out_size;

    float *wf, *h, *wt, *hw, *hb;
    cudaGetSymbolAddress((void**)&wf, g_wf);
    cudaGetSymbolAddress((void**)&h,  g_h);
    cudaGetSymbolAddress((void**)&wt, g_wt);
    cudaGetSymbolAddress((void**)&hw, g_hw);
    cudaGetSymbolAddress((void**)&hb, g_hb);

    float* wcl = (float*)d_out;                        // [M, 64]
    float* bin = (float*)d_out + (size_t)M_ * NMUT;    // [M, 32]

    const int SMEM_MAIN = 2 * (128 * 40 + 128 * 40) * 4;   // 81920
    const int SMEM_HEAD = 2 * (64 * 40 + 96 * 40) * 4;     // 51200
    cudaFuncSetAttribute(tc_main, cudaFuncAttributeMaxDynamicSharedMemorySize, SMEM_MAIN);
    cudaFuncSetAttribute(tc_head, cudaFuncAttributeMaxDynamicSharedMemorySize, SMEM_HEAD);

    scan_kernel<<<B_, 256>>>(wstarts);
    wf_kernel<<<M_, 256>>>(features);
    roundw_kernel<<<D_ * D_ / 4 / 256, 256>>>(dense_w);
    headw_copy<<<NMUT * D_ / 4 / 256, 256>>>(out_w, out_b);
    headw_bin<<<8, 256>>>(out_w, out_b, bin_w, bin_b);

    tc_main<<<dim3(8, MPAD / 128), 256, SMEM_MAIN>>>(wf, wt, dense_b, h);
    tc_head<<<MPAD / 64, 256, SMEM_HEAD>>>(h, hw, hb, wcl, bin);
}

// round 9
// speedup vs baseline: 1.0990x; 1.0232x over previous
#include <cuda_runtime.h>
#include <cstdint>

#define B_    16
#define T_    2048
#define D_    1024
#define TT_   2046
#define MW_   682
#define M_    (B_ * MW_)          // 10912
#define MPAD  11008               // 86 * 128 = 172 * 64
#define NMUT  64
#define NBIN  32
#define NHEAD 96                  // 64 class + 32 binary (fused)

// NOTE: all GEMM operand tensors below are stored with each 8-wide k-group
// permuted: logical k -> storage position p(k) = 2*(k&3) | (k>>2).
// This makes mma fragment k-pairs (tg, tg+4) adjacent -> LDS.64 loads.
__device__ float g_wf[MPAD * D_];        // word features, tf32, k-permuted
__device__ float g_h [MPAD * D_];        // tanh hidden, tf32, k-permuted
__device__ float g_wt[D_ * D_];          // dense_w, tf32, k-permuted
__device__ float g_hw[NHEAD * D_];       // fused head weights, tf32, k-permuted
__device__ float g_hb[NHEAD];            // fused head bias
__device__ int   g_begin[M_];
__device__ int   g_cnt  [M_];

// ===========================================================================
// helpers
// ===========================================================================
__device__ __forceinline__ uint32_t smem_u32(const void* p) {
    return (uint32_t)__cvta_generic_to_shared(p);
}
__device__ __forceinline__ void cp16(uint32_t dst, const void* src) {
    asm volatile("cp.async.cg.shared.global [%0], [%1], 16;\n" :: "r"(dst), "l"(src));
}
#define CP_COMMIT() asm volatile("cp.async.commit_group;" ::: "memory")

__device__ __forceinline__ float f2tf(float x) {
    uint32_t r;
    asm("cvt.rna.tf32.f32 %0, %1;" : "=r"(r) : "f"(x));
    return __uint_as_float(r);
}
__device__ __forceinline__ float tanh_fast(float x) {
    float y;
    asm("tanh.approx.f32 %0, %1;" : "=f"(y) : "f"(x));
    return y;
}
__device__ __forceinline__ int kperm8(int l) {       // l in 0..7
    return ((l & 3) << 1) | (l >> 2);
}
__device__ __forceinline__ void mma8(float* c, const uint32_t* a, const uint32_t* b) {
    asm volatile("mma.sync.aligned.m16n8k8.row.col.f32.tf32.tf32.f32 "
        "{%0,%1,%2,%3}, {%4,%5,%6,%7}, {%8,%9}, {%0,%1,%2,%3};"
        : "+f"(c[0]), "+f"(c[1]), "+f"(c[2]), "+f"(c[3])
        : "r"(a[0]), "r"(a[1]), "r"(a[2]), "r"(a[3]), "r"(b[0]), "r"(b[1]));
}

// ===========================================================================
// 1) per-batch scan of word_starts -> word begin token + token count
// ===========================================================================
__global__ void scan_kernel(const int* __restrict__ ws) {
    int b = blockIdx.x;
    const int* w = ws + b * TT_;
    __shared__ int partial[256];
    __shared__ int scnt[MW_];
    int tid = threadIdx.x;
    for (int i = tid; i < MW_; i += 256) scnt[i] = 0;

    int vals[8];
    int s = 0;
#pragma unroll
    for (int i = 0; i < 8; i++) {
        int t = tid * 8 + i;
        int v = (t < TT_) ? w[t] : 0;
        vals[i] = v; s += v;
    }
    partial[tid] = s;
    __syncthreads();
    for (int off = 1; off < 256; off <<= 1) {
        int v = partial[tid];
        int add = (tid >= off) ? partial[tid - off] : 0;
        __syncthreads();
        partial[tid] = v + add;
        __syncthreads();
    }
    int run = (tid > 0) ? partial[tid - 1] : 0;
#pragma unroll
    for (int i = 0; i < 8; i++) {
        int t = tid * 8 + i;
        if (t < TT_) {
            run += vals[i];
            int seg = run - 1;
            if (seg >= 0 && seg < MW_) {
                if (vals[i]) g_begin[b * MW_ + seg] = t;
                atomicAdd(&scnt[seg], 1);
            }
        }
    }
    __syncthreads();
    for (int i = tid; i < MW_; i += 256) g_cnt[b * MW_ + i] = scnt[i];
}

// ===========================================================================
// 2) word-feature segment sums, tf32-rounded, k-permuted store
// ===========================================================================
__global__ void wf_kernel(const float* __restrict__ feat) {
    int m = blockIdx.x;
    int b = m / MW_;
    int tid = threadIdx.x;                       // float4 index 0..255
    int cnt = g_cnt[m];
    float* orow = g_wf + (size_t)m * D_;
    int base8 = (4 * tid) & ~7;
    int o = tid & 1;
    float* dst = orow + base8 + o;
    if (cnt == 0) {
        float one = f2tf(1.f);
        dst[0] = one; dst[2] = one; dst[4] = one; dst[6] = one;
        return;
    }
    int t0 = g_begin[m];
    const float4* base = (const float4*)(feat + ((size_t)b * T_ + 1 + t0) * D_);
    float4 acc = base[tid];
    for (int i = 1; i < cnt; i++) {
        float4 v = base[(size_t)i * (D_ / 4) + tid];
        acc.x += v.x; acc.y += v.y; acc.z += v.z; acc.w += v.w;
    }
    dst[0] = f2tf(acc.x); dst[2] = f2tf(acc.y);
    dst[4] = f2tf(acc.z); dst[6] = f2tf(acc.w);
}

// ===========================================================================
// 2b) combined tf32 round-copy of dense_w (k-perm) and g_hw rows 0..63
// ===========================================================================
__global__ void prep_kernel(const float* __restrict__ dense_w,
                            const float* __restrict__ out_w,
                            const float* __restrict__ out_b) {
    int i = blockIdx.x * 256 + threadIdx.x;      // float4 index
    const int NW = D_ * D_ / 4;                  // 262144
    if (i < NW) {
        float4 v = ((const float4*)dense_w)[i];
        int base8 = (4 * i) & ~7;
        int o = i & 1;
        float* dst = g_wt + base8 + o;
        dst[0] = f2tf(v.x); dst[2] = f2tf(v.y); dst[4] = f2tf(v.z); dst[6] = f2tf(v.w);
    } else {
        int j = i - NW;                          // over 64*1024/4 = 16384
        float4 v = ((const float4*)out_w)[j];
        int base8 = (4 * j) & ~7;
        int o = j & 1;
        float* dst = g_hw + base8 + o;
        dst[0] = f2tf(v.x); dst[2] = f2tf(v.y); dst[4] = f2tf(v.z); dst[6] = f2tf(v.w);
        if (j < NMUT) g_hb[j] = out_b[j];
    }
}

// ===========================================================================
// 3) g_hw rows 64..95 = round(bin_w[:,64:] + bin_w[:,:64] @ out_w), k-permuted
//    g_hb[64..95]     = bin_b + bin_w[:,:64] @ out_b
// ===========================================================================
__global__ void headw_bin(const float* __restrict__ out_w, const float* __restrict__ out_b,
                          const float* __restrict__ bin_w, const float* __restrict__ bin_b) {
    __shared__ float w1[NBIN][NMUT];
    int tid = threadIdx.x;
    int col0 = blockIdx.x * 128;
    for (int i = tid; i < NBIN * NMUT; i += 256) {
        int r = i >> 6, j = i & 63;
        w1[r][j] = bin_w[(size_t)r * (D_ + NMUT) + j];
    }
    __syncthreads();

    int col = col0 + (tid & 127);
    int rh  = (tid >> 7) * 16;
    float acc[16];
#pragma unroll
    for (int r = 0; r < 16; r++)
        acc[r] = bin_w[(size_t)(rh + r) * (D_ + NMUT) + NMUT + col];
    for (int j = 0; j < NMUT; j++) {
        float v = out_w[(size_t)j * D_ + col];
#pragma unroll
        for (int r = 0; r < 16; r++) acc[r] += w1[rh + r][j] * v;
    }
    int pc = (col & ~7) | kperm8(col & 7);
#pragma unroll
    for (int r = 0; r < 16; r++)
        g_hw[(size_t)(NMUT + rh + r) * D_ + pc] = f2tf(acc[r]);

    if (blockIdx.x == 0 && tid < NBIN) {
        float bb = bin_b[tid];
        for (int j = 0; j < NMUT; j++) bb += w1[tid][j] * out_b[j];
        g_hb[NMUT + tid] = bb;
    }
}

// ===========================================================================
// 4) main tf32 GEMM: h = tanh(wf @ wt^T + b), 128x128 tile, BK=32, 2-stage.
//    Operands k-permuted => LDS.64 fragment loads. Row stride 40.
//    Epilogue uses HW tanh.approx (MUFU.TANH).
// ===========================================================================
__global__ __launch_bounds__(256) void tc_main(
    const float* __restrict__ A, const float* __restrict__ Bw,
    const float* __restrict__ bias, float* __restrict__ O1)
{
    constexpr int AST = 128 * 40;
    constexpr int BST = 128 * 40;
    extern __shared__ float smem[];
    float* Asm = smem;                           // [2][128][40]
    float* Bsm = smem + 2 * AST;                 // [2][128][40]

    const int tid = threadIdx.x;
    const int lane = tid & 31, wid = tid >> 5;
    const int g = lane >> 2, tg = lane & 3;
    const int wm = (wid & 3) * 32;
    const int wn = (wid >> 2) * 64;
    const int row0 = blockIdx.y * 128;
    const int col0 = blockIdx.x * 128;

    float acc[2][8][4];
#pragma unroll
    for (int i = 0; i < 2; i++)
#pragma unroll
        for (int j = 0; j < 8; j++)
#pragma unroll
            for (int q = 0; q < 4; q++) acc[i][j][q] = 0.f;

    const float* Ab = A + (size_t)row0 * D_;
    const float* Bb = Bw + (size_t)col0 * D_;

    auto loadStage = [&](int st, int k0) {
        float* Ad = Asm + st * AST;
#pragma unroll
        for (int i = tid; i < 1024; i += 256) {
            int r = i >> 3, c = i & 7;
            cp16(smem_u32(Ad + r * 40 + c * 4), Ab + (size_t)r * D_ + k0 + c * 4);
        }
        float* Bd = Bsm + st * BST;
#pragma unroll
        for (int i = tid; i < 1024; i += 256) {
            int r = i >> 3, c = i & 7;
            cp16(smem_u32(Bd + r * 40 + c * 4), Bb + (size_t)r * D_ + k0 + c * 4);
        }
        CP_COMMIT();
    };
    auto compute = [&](int st) {
        const float* Ad = Asm + st * AST;
        const float* Bd = Bsm + st * BST;
#pragma unroll
        for (int ks = 0; ks < 4; ks++) {
            const int kk = ks * 8 + 2 * tg;
            uint32_t a[2][4];
#pragma unroll
            for (int i = 0; i < 2; i++) {
                const float* ap = Ad + (wm + i * 16 + g) * 40 + kk;
                uint2 v0 = *(const uint2*)ap;            // k=tg, k=tg+4
                uint2 v1 = *(const uint2*)(ap + 8 * 40);
                a[i][0] = v0.x; a[i][2] = v0.y;
                a[i][1] = v1.x; a[i][3] = v1.y;
            }
#pragma unroll
            for (int j = 0; j < 8; j++) {
                const float* bp = Bd + (wn + j * 8 + g) * 40 + kk;
                uint2 vb = *(const uint2*)bp;
                uint32_t b[2] = { vb.x, vb.y };
                mma8(acc[0][j], a[0], b);
                mma8(acc[1][j], a[1], b);
            }
        }
    };

    loadStage(0, 0);
    int st = 0;
    for (int k0 = 0; k0 < D_; k0 += 32) {
        asm volatile("cp.async.wait_group 0;" ::: "memory");
        __syncthreads();
        if (k0 + 32 < D_) loadStage(st ^ 1, k0 + 32);
        compute(st);
        st ^= 1;
    }

    // epilogue: bias + tanh.approx, tf32-round, k-permuted scalar stores
#pragma unroll
    for (int i = 0; i < 2; i++) {
#pragma unroll
        for (int j = 0; j < 8; j++) {
            int r = row0 + wm + i * 16 + g;
            int c = col0 + wn + j * 8 + tg * 2;
            int cb = c & ~7;
            int p0 = cb + kperm8(c & 7);
            int p1 = cb + kperm8((c + 1) & 7);
            float x0 = f2tf(tanh_fast(acc[i][j][0] + bias[c]));
            float x1 = f2tf(tanh_fast(acc[i][j][1] + bias[c + 1]));
            float x2 = f2tf(tanh_fast(acc[i][j][2] + bias[c]));
            float x3 = f2tf(tanh_fast(acc[i][j][3] + bias[c + 1]));
            O1[(size_t)r * D_ + p0] = x0;
            O1[(size_t)r * D_ + p1] = x1;
            O1[(size_t)(r + 8) * D_ + p0] = x2;
            O1[(size_t)(r + 8) * D_ + p1] = x3;
        }
    }
}

// ===========================================================================
// 5) head GEMM: [wcl|bin] = h @ g_hw^T + g_hb.  BM=64, BN=96, BK=32,
//    grid 172 blocks, 8 warps (2m x 4n), warp tile 32x24 (NF=3).
// ===========================================================================
__global__ __launch_bounds__(256) void tc_head(
    const float* __restrict__ A, const float* __restrict__ Bw,
    const float* __restrict__ bias,
    float* __restrict__ O1, float* __restrict__ O2)
{
    constexpr int AST = 64 * 40;
    constexpr int BST = 96 * 40;
    extern __shared__ float smem[];
    float* Asm = smem;                           // [2][64][40]
    float* Bsm = smem + 2 * AST;                 // [2][96][40]

    const int tid = threadIdx.x;
    const int lane = tid & 31, wid = tid >> 5;
    const int g = lane >> 2, tg = lane & 3;
    const int wm = (wid & 1) * 32;
    const int wn = (wid >> 1) * 24;
    const int row0 = blockIdx.x * 64;

    float acc[2][3][4];
#pragma unroll
    for (int i = 0; i < 2; i++)
#pragma unroll
        for (int j = 0; j < 3; j++)
#pragma unroll
            for (int q = 0; q < 4; q++) acc[i][j][q] = 0.f;

    const float* Ab = A + (size_t)row0 * D_;

    auto loadStage = [&](int st, int k0) {
        float* Ad = Asm + st * AST;
#pragma unroll
        for (int i = tid; i < 512; i += 256) {
            int r = i >> 3, c = i & 7;
            cp16(smem_u32(Ad + r * 40 + c * 4), Ab + (size_t)r * D_ + k0 + c * 4);
        }
        float* Bd = Bsm + st * BST;
#pragma unroll
        for (int i = tid; i < 768; i += 256) {
            int r = i >> 3, c = i & 7;
            cp16(smem_u32(Bd + r * 40 + c * 4), Bw + (size_t)r * D_ + k0 + c * 4);
        }
        CP_COMMIT();
    };
    auto compute = [&](int st) {
        const float* Ad = Asm + st * AST;
        const float* Bd = Bsm + st * BST;
#pragma unroll
        for (int ks = 0; ks < 4; ks++) {
            const int kk = ks * 8 + 2 * tg;
            uint32_t a[2][4];
#pragma unroll
            for (int i = 0; i < 2; i++) {
                const float* ap = Ad + (wm + i * 16 + g) * 40 + kk;
                uint2 v0 = *(const uint2*)ap;
                uint2 v1 = *(const uint2*)(ap + 8 * 40);
                a[i][0] = v0.x; a[i][2] = v0.y;
                a[i][1] = v1.x; a[i][3] = v1.y;
            }
#pragma unroll
            for (int j = 0; j < 3; j++) {
                const float* bp = Bd + (wn + j * 8 + g) * 40 + kk;
                uint2 vb = *(const uint2*)bp;
                uint32_t b[2] = { vb.x, vb.y };
                mma8(acc[0][j], a[0], b);
                mma8(acc[1][j], a[1], b);
            }
        }
    };

    loadStage(0, 0);
    int st = 0;
    for (int k0 = 0; k0 < D_; k0 += 32) {
        asm volatile("cp.async.wait_group 0;" ::: "memory");
        __syncthreads();
        if (k0 + 32 < D_) loadStage(st ^ 1, k0 + 32);
        compute(st);
        st ^= 1;
    }

#pragma unroll
    for (int i = 0; i < 2; i++) {
#pragma unroll
        for (int j = 0; j < 3; j++) {
            int c = wn + j * 8 + tg * 2;
#pragma unroll
            for (int rr = 0; rr < 2; rr++) {
                int row = row0 + wm + i * 16 + g + rr * 8;
                if (row < M_) {
                    float x0 = acc[i][j][rr * 2 + 0] + bias[c];
                    float x1 = acc[i][j][rr * 2 + 1] + bias[c + 1];
                    if (c < NMUT) {
                        O1[(size_t)row * NMUT + c] = x0;
                        O1[(size_t)row * NMUT + c + 1] = x1;
                    } else {
                        O2[(size_t)row * NBIN + (c - NMUT)] = x0;
                        O2[(size_t)row * NBIN + (c - NMUT) + 1] = x1;
                    }
                }
            }
        }
    }
}

// ===========================================================================
extern "C" void kernel_launch(void* const* d_in, const int* in_sizes, int n_in,
                              void* d_out, int out_size)
{
    const float* features = (const float*)d_in[0];
    const int*   wstarts  = (const int*)d_in[1];
    const float* dense_w  = (const float*)d_in[2];
    const float* dense_b  = (const float*)d_in[3];
    const float* out_w    = (const float*)d_in[4];
    const float* out_b    = (const float*)d_in[5];
    const float* bin_w    = (const float*)d_in[6];
    const float* bin_b    = (const float*)d_in[7];
    (void)in_sizes; (void)n_in; (void)out_size;

    float *wf, *h, *wt, *hw, *hb;
    cudaGetSymbolAddress((void**)&wf, g_wf);
    cudaGetSymbolAddress((void**)&h,  g_h);
    cudaGetSymbolAddress((void**)&wt, g_wt);
    cudaGetSymbolAddress((void**)&hw, g_hw);
    cudaGetSymbolAddress((void**)&hb, g_hb);

    float* wcl = (float*)d_out;                        // [M, 64]
    float* bin = (float*)d_out + (size_t)M_ * NMUT;    // [M, 32]

    const int SMEM_MAIN = 2 * (128 * 40 + 128 * 40) * 4;   // 81920
    const int SMEM_HEAD = 2 * (64 * 40 + 96 * 40) * 4;     // 51200
    cudaFuncSetAttribute(tc_main, cudaFuncAttributeMaxDynamicSharedMemorySize, SMEM_MAIN);
    cudaFuncSetAttribute(tc_head, cudaFuncAttributeMaxDynamicSharedMemorySize, SMEM_HEAD);

    scan_kernel<<<B_, 256>>>(wstarts);
    wf_kernel<<<M_, 256>>>(features);
    prep_kernel<<<(D_ * D_ / 4 + NMUT * D_ / 4 + 255) / 256, 256>>>(dense_w, out_w, out_b);
    headw_bin<<<8, 256>>>(out_w, out_b, bin_w, bin_b);

    tc_main<<<dim3(8, MPAD / 128), 256, SMEM_MAIN>>>(wf, wt, dense_b, h);
    tc_head<<<MPAD / 64, 256, SMEM_HEAD>>>(h, hw, hb, wcl, bin);
}